// round 3
// baseline (speedup 1.0000x reference)
#include <cuda_runtime.h>
#include <math.h>

// Problem dims (fixed)
#define Bsz   128
#define Tlen  512
#define Isz   256
#define Hsz   512
#define Osz   256
#define NBT   8      // number of batch tiles
#define BTW   16     // batch tile width (NBT*BTW = Bsz)
#define RNN_BLOCKS 128

// Scratch (device globals; no runtime allocation)
__device__ float    g_xp[(size_t)Tlen * NBT * Hsz * BTW]; // [t][bt][h][16]  (= 128 MB)
__device__ float    g_h[2][NBT * Hsz * BTW];              // [parity][bt][k][16]
__device__ unsigned g_bar_count = 0;
__device__ unsigned g_bar_gen   = 0;

// ---------------------------------------------------------------------------
// h init: g_h[0][bt][k][b] = h0[k]
// ---------------------------------------------------------------------------
__global__ void hinit_kernel(const float* __restrict__ h0) {
    int idx = blockIdx.x * blockDim.x + threadIdx.x;   // over 8*512*16 = 65536
    int k = (idx >> 4) & (Hsz - 1);
    g_h[0][idx] = h0[k];
}

// ---------------------------------------------------------------------------
// x_proj: xp[t][bt][h][b] = sum_i inputs[b][t][i]*W_ih[h][i] + b_ih[h] + b_hh[h]
// grid: (Tlen/TQ, NBT, Hsz/32), block 128 threads. Dyn smem: Wt[256][32] + xs[16][260]
// ---------------------------------------------------------------------------
#define TQ  4
#define XSP 260

__global__ void __launch_bounds__(128, 1) xp_kernel(
    const float* __restrict__ inputs, const float* __restrict__ W_ih,
    const float* __restrict__ b_ih,   const float* __restrict__ b_hh)
{
    extern __shared__ float smem[];
    float* Wt = smem;                 // [256][32] : Wt[i*32+j] = W_ih[h0+j][i]
    float* xs = smem + 256 * 32;      // [16][XSP] : xs[b*XSP+i] = inputs[b0+b][t][i]

    const int tq = blockIdx.x, bt = blockIdx.y, ht = blockIdx.z;
    const int h0 = ht * 32, b0 = bt * BTW;
    const int tid = threadIdx.x;
    const int lane_j = tid & 31;      // h column within tile
    const int qb = tid >> 5;          // 0..3

    // Stage W_ih tile transposed (conflict-free STS; one-time per block)
    for (int q = qb; q < 64; q += 4) {
        float4 w = *(const float4*)&W_ih[(h0 + lane_j) * Isz + 4 * q];
        Wt[(4*q+0)*32 + lane_j] = w.x;
        Wt[(4*q+1)*32 + lane_j] = w.y;
        Wt[(4*q+2)*32 + lane_j] = w.z;
        Wt[(4*q+3)*32 + lane_j] = w.w;
    }

    const int b_ = tid & 15, hg = tid >> 4;    // hg 0..7, thread owns 4 h rows
    float bias0 = b_ih[h0+hg*4+0] + b_hh[h0+hg*4+0];
    float bias1 = b_ih[h0+hg*4+1] + b_hh[h0+hg*4+1];
    float bias2 = b_ih[h0+hg*4+2] + b_hh[h0+hg*4+2];
    float bias3 = b_ih[h0+hg*4+3] + b_hh[h0+hg*4+3];

    for (int tt = 0; tt < TQ; tt++) {
        int t = tq * TQ + tt;
        __syncthreads();  // protects xs reuse (and first-iter Wt)
        // Stage x tile: 16 rows x 256 floats, coalesced float4 loads
        for (int idx = tid; idx < 16 * 64; idx += 128) {
            int r = idx >> 6, q = idx & 63;
            float4 x = *(const float4*)&inputs[((size_t)(b0 + r) * Tlen + t) * Isz + 4 * q];
            // scalar stores (row stride 260 keeps reads conflict-free)
            xs[r*XSP + 4*q+0] = x.x; xs[r*XSP + 4*q+1] = x.y;
            xs[r*XSP + 4*q+2] = x.z; xs[r*XSP + 4*q+3] = x.w;
        }
        __syncthreads();

        float acc0 = 0.f, acc1 = 0.f, acc2 = 0.f, acc3 = 0.f;
        #pragma unroll 8
        for (int i = 0; i < Isz; i++) {
            float a = xs[b_ * XSP + i];
            float4 w = *(const float4*)&Wt[i * 32 + hg * 4];
            acc0 += a * w.x; acc1 += a * w.y; acc2 += a * w.z; acc3 += a * w.w;
        }
        float* dst = &g_xp[(((size_t)t * NBT + bt) * Hsz + h0 + hg * 4) * BTW + b_];
        dst[0]  = acc0 + bias0;
        dst[16] = acc1 + bias1;
        dst[32] = acc2 + bias2;
        dst[48] = acc3 + bias3;
    }
}

// ---------------------------------------------------------------------------
// Persistent recurrence kernel. 128 blocks (16 h-tiles x 8 b-tiles), 128 thr.
// Dyn smem: Wt[512][32] (W_hh tile, staged once) + hs[512][16] (h state slice)
// Per step: full-chip GEMM 128x512x512, epilogue h+=tanh(.)*invT, grid barrier.
// ---------------------------------------------------------------------------
__global__ void __launch_bounds__(128, 1) rnn_kernel(const float* __restrict__ W_hh)
{
    extern __shared__ float smem[];
    float* Wt = smem;                  // [512][32]: Wt[k*32+j] = W_hh[h0+j][k]
    float* hs = smem + Hsz * 32;       // [512][16]: hs[k*16+b] = h[k][b0+b]

    const int blk = blockIdx.x;
    const int ht = blk & 15, bt = blk >> 4;
    const int h0 = ht * 32;
    const int tid = threadIdx.x;
    const int lane_j = tid & 31;
    const int qb = tid >> 5;

    // Stage W_hh tile once, transposed (reused for all 512 steps)
    for (int q = qb; q < 128; q += 4) {
        float4 w = *(const float4*)&W_hh[(h0 + lane_j) * Hsz + 4 * q];
        Wt[(4*q+0)*32 + lane_j] = w.x;
        Wt[(4*q+1)*32 + lane_j] = w.y;
        Wt[(4*q+2)*32 + lane_j] = w.z;
        Wt[(4*q+3)*32 + lane_j] = w.w;
    }

    const int b_ = tid & 15, hg = tid >> 4;
    const float invT = 1.0f / 512.0f;

    unsigned base_gen = 0;
    if (tid == 0) base_gen = *(volatile unsigned*)&g_bar_gen;  // safe: read before any release

    for (int t = 0; t < Tlen; t++) {
        const float4* hsrc = (const float4*)(g_h[t & 1] + bt * (Hsz * BTW));
        __syncthreads();   // prior-iter epilogue reads of hs done; covers Wt on iter 0
        // Stage this block's h slice (32 KB), L2-sourced (bypass possibly-stale L1)
        for (int idx = tid; idx < (Hsz * BTW) / 4; idx += 128) {
            float4 v = __ldcg(hsrc + idx);
            *((float4*)hs + idx) = v;
        }
        __syncthreads();

        float acc0 = 0.f, acc1 = 0.f, acc2 = 0.f, acc3 = 0.f;
        #pragma unroll 8
        for (int k = 0; k < Hsz; k++) {
            float a = hs[k * 16 + b_];
            float4 w = *(const float4*)&Wt[k * 32 + hg * 4];
            acc0 += a * w.x; acc1 += a * w.y; acc2 += a * w.z; acc3 += a * w.w;
        }

        // Epilogue: h_new = h + tanh(acc + xp)*invT
        const float* xpp = &g_xp[(((size_t)t * NBT + bt) * Hsz + h0 + hg * 4) * BTW + b_];
        float* hdst = g_h[(t + 1) & 1] + bt * (Hsz * BTW) + (h0 + hg * 4) * BTW + b_;
        float hp0 = hs[(h0 + hg*4 + 0) * 16 + b_];
        float hp1 = hs[(h0 + hg*4 + 1) * 16 + b_];
        float hp2 = hs[(h0 + hg*4 + 2) * 16 + b_];
        float hp3 = hs[(h0 + hg*4 + 3) * 16 + b_];
        hdst[0]  = hp0 + tanhf(acc0 + xpp[0])  * invT;
        hdst[16] = hp1 + tanhf(acc1 + xpp[16]) * invT;
        hdst[32] = hp2 + tanhf(acc2 + xpp[32]) * invT;
        hdst[48] = hp3 + tanhf(acc3 + xpp[48]) * invT;

        // Grid barrier (sense via monotonic generation counter)
        __syncthreads();
        if (tid == 0) {
            __threadfence();
            unsigned target = base_gen + (unsigned)(t + 1);
            if (atomicAdd(&g_bar_count, 1u) == RNN_BLOCKS - 1) {
                atomicExch(&g_bar_count, 0u);
                __threadfence();
                atomicExch(&g_bar_gen, target);
            } else {
                while ((*(volatile unsigned*)&g_bar_gen) - base_gen < (unsigned)(t + 1)) { }
            }
        }
        __syncthreads();
    }
}

// ---------------------------------------------------------------------------
// Readout: out[b][o] = sum_k h_last[k][b] * W_out[o][k] + b_out[o]
// grid 64 blocks (8 o-tiles x 8 b-tiles), 128 threads. Same tiling as rnn.
// ---------------------------------------------------------------------------
__global__ void __launch_bounds__(128, 1) out_kernel(
    const float* __restrict__ W_out, const float* __restrict__ b_out,
    float* __restrict__ out)
{
    extern __shared__ float smem[];
    float* Wt = smem;                  // [512][32]
    float* hs = smem + Hsz * 32;       // [512][16]

    const int blk = blockIdx.x;
    const int ot = blk & 7, bt = blk >> 3;
    const int o0 = ot * 32;
    const int tid = threadIdx.x;
    const int lane_j = tid & 31;
    const int qb = tid >> 5;

    for (int q = qb; q < 128; q += 4) {
        float4 w = *(const float4*)&W_out[(o0 + lane_j) * Hsz + 4 * q];
        Wt[(4*q+0)*32 + lane_j] = w.x;
        Wt[(4*q+1)*32 + lane_j] = w.y;
        Wt[(4*q+2)*32 + lane_j] = w.z;
        Wt[(4*q+3)*32 + lane_j] = w.w;
    }
    const float4* hsrc = (const float4*)(g_h[0] + bt * (Hsz * BTW));  // final state parity = 0
    for (int idx = tid; idx < (Hsz * BTW) / 4; idx += 128) {
        *((float4*)hs + idx) = hsrc[idx];
    }
    __syncthreads();

    const int b_ = tid & 15, og = tid >> 4;
    float acc0 = 0.f, acc1 = 0.f, acc2 = 0.f, acc3 = 0.f;
    #pragma unroll 8
    for (int k = 0; k < Hsz; k++) {
        float a = hs[k * 16 + b_];
        float4 w = *(const float4*)&Wt[k * 32 + og * 4];
        acc0 += a * w.x; acc1 += a * w.y; acc2 += a * w.z; acc3 += a * w.w;
    }
    int b_glob = bt * BTW + b_;
    int o = o0 + og * 4;
    out[b_glob * Osz + o + 0] = acc0 + b_out[o + 0];
    out[b_glob * Osz + o + 1] = acc1 + b_out[o + 1];
    out[b_glob * Osz + o + 2] = acc2 + b_out[o + 2];
    out[b_glob * Osz + o + 3] = acc3 + b_out[o + 3];
}

// ---------------------------------------------------------------------------
extern "C" void kernel_launch(void* const* d_in, const int* in_sizes, int n_in,
                              void* d_out, int out_size)
{
    const float* inputs = (const float*)d_in[0];
    const float* W_ih   = (const float*)d_in[1];
    const float* b_ih   = (const float*)d_in[2];
    const float* W_hh   = (const float*)d_in[3];
    const float* b_hh   = (const float*)d_in[4];
    const float* W_out  = (const float*)d_in[5];
    const float* b_out  = (const float*)d_in[6];
    const float* h0     = (const float*)d_in[7];
    float* out = (float*)d_out;

    const int SMEM_XP  = (256 * 32 + 16 * XSP) * 4;   // 49408 B
    const int SMEM_RNN = (Hsz * 32 + Hsz * BTW) * 4;  // 98304 B
    cudaFuncSetAttribute(xp_kernel,  cudaFuncAttributeMaxDynamicSharedMemorySize, SMEM_XP);
    cudaFuncSetAttribute(rnn_kernel, cudaFuncAttributeMaxDynamicSharedMemorySize, SMEM_RNN);
    cudaFuncSetAttribute(out_kernel, cudaFuncAttributeMaxDynamicSharedMemorySize, SMEM_RNN);

    hinit_kernel<<<64, 1024>>>(h0);
    xp_kernel<<<dim3(Tlen / TQ, NBT, Hsz / 32), 128, SMEM_XP>>>(inputs, W_ih, b_ih, b_hh);
    rnn_kernel<<<RNN_BLOCKS, 128, SMEM_RNN>>>(W_hh);
    out_kernel<<<64, 128, SMEM_RNN>>>(W_out, b_out, out);
}

// round 4
// speedup vs baseline: 1.2066x; 1.2066x over previous
#include <cuda_runtime.h>
#include <math.h>

// Problem dims (fixed)
#define Bsz   128
#define Tlen  512
#define Isz   256
#define Hsz   512
#define Osz   256
#define NBT   8      // number of batch tiles
#define BTW   16     // batch tile width (NBT*BTW = Bsz)
#define RNN_BLOCKS 128

// Packed f32x2 helpers (ptxas never emits FFMA2 from C++; inline PTX required)
#define FMA2(acc, a, b) \
    asm("fma.rn.f32x2 %0, %1, %2, %0;" : "+l"(acc) : "l"(a), "l"(b))
#define ADD2(d, a, b) \
    asm("add.rn.f32x2 %0, %1, %2;" : "=l"(d) : "l"(a), "l"(b))
#define PACK2(d, lo, hi) \
    asm("mov.b64 %0, {%1, %2};" : "=l"(d) : "f"(lo), "f"(hi))
#define UNPACK2(lo, hi, v) \
    asm("mov.b64 {%0, %1}, %2;" : "=f"(lo), "=f"(hi) : "l"(v))

typedef unsigned long long u64;

// Scratch (device globals; no runtime allocation)
__device__ float    g_xp[(size_t)Tlen * NBT * Hsz * BTW]; // [t][bt][h][16]
__device__ float    g_h[2][NBT * Hsz * BTW];              // [parity][bt][k][16]
__device__ unsigned g_bar_count = 0;
__device__ unsigned g_bar_gen   = 0;

// ---------------------------------------------------------------------------
// h init: g_h[0][bt][k][b] = h0[k]
// ---------------------------------------------------------------------------
__global__ void hinit_kernel(const float* __restrict__ h0) {
    int idx = blockIdx.x * blockDim.x + threadIdx.x;   // over 8*512*16 = 65536
    int k = (idx >> 4) & (Hsz - 1);
    g_h[0][idx] = h0[k];
}

// ---------------------------------------------------------------------------
// x_proj: xp[t][bt][h][b] = sum_i inputs[b][t][i]*W_ih[h][i] + b_ih[h]+b_hh[h]
// grid (Tlen/TQ, NBT, Hsz/32), 256 threads. FFMA2, I-split 4.
// smem: Wt[256][32] f32 (32KB) + xs2[16][257] u64 (32.9KB) + red[1024] u64 (8KB)
// ---------------------------------------------------------------------------
#define TQ  4
#define XSROW 257

__global__ void __launch_bounds__(256) xp_kernel(
    const float* __restrict__ inputs, const float* __restrict__ W_ih,
    const float* __restrict__ b_ih,   const float* __restrict__ b_hh)
{
    extern __shared__ float smem[];
    float* Wt  = smem;                              // [256][32]: Wt[i][j]=W_ih[h0+j][i]
    u64*   xs2 = (u64*)(smem + 8192);               // [16][257]: xs2[b][i]={x,x}
    u64*   red = (u64*)(smem + 8192 + 2 * 16 * XSROW);  // [4][16][16]
    const u64* Wtu = (const u64*)Wt;

    const int tq = blockIdx.x, bt = blockIdx.y, ht = blockIdx.z;
    const int h0 = ht * 32, b0 = bt * BTW;
    const int tid = threadIdx.x;

    // Stage W_ih tile transposed (once)
    {
        const int lane_j = tid & 31, qb = tid >> 5;          // qb 0..7
        for (int r = 0; r < 8; r++) {
            int q = qb + 8 * r;                              // 0..63
            float4 w = *(const float4*)&W_ih[(h0 + lane_j) * Isz + 4 * q];
            Wt[(4*q+0)*32 + lane_j] = w.x;
            Wt[(4*q+1)*32 + lane_j] = w.y;
            Wt[(4*q+2)*32 + lane_j] = w.z;
            Wt[(4*q+3)*32 + lane_j] = w.w;
        }
    }

    const int bg = tid & 7, hg = (tid >> 3) & 7, is = tid >> 6;  // I-split 0..3
    // Phase-2 assignment: one (hp, b) pair per thread
    const int pb = tid & 15, php = tid >> 4;                     // 0..15 each
    const float pbias0 = b_ih[h0 + php*2 + 0] + b_hh[h0 + php*2 + 0];
    const float pbias1 = b_ih[h0 + php*2 + 1] + b_hh[h0 + php*2 + 1];

    for (int tt = 0; tt < TQ; tt++) {
        const int t = tq * TQ + tt;
        __syncthreads();   // xs2/red reuse; covers Wt on first iter
        // Stage x tile replicated: xs2[b][i] = {x[b][t][i], x[b][t][i]}
        for (int j = 0; j < 4; j++) {
            int idx = tid + 256 * j;                 // 1024 float4 loads
            int r = idx >> 6, q = idx & 63;
            float4 x = *(const float4*)&inputs[((size_t)(b0 + r) * Tlen + t) * Isz + 4 * q];
            u64 p0, p1, p2, p3;
            PACK2(p0, x.x, x.x); PACK2(p1, x.y, x.y);
            PACK2(p2, x.z, x.z); PACK2(p3, x.w, x.w);
            u64* dst = &xs2[r * XSROW + 4 * q];
            dst[0] = p0; dst[1] = p1; dst[2] = p2; dst[3] = p3;
        }
        __syncthreads();

        u64 a00 = 0, a10 = 0, a01 = 0, a11 = 0;     // [hpair][b]
        const u64* xr0 = &xs2[(2 * bg + 0) * XSROW + is * 64];
        const u64* xr1 = &xs2[(2 * bg + 1) * XSROW + is * 64];
        const u64* wr  = &Wtu[(is * 64) * 16 + hg * 2];
        #pragma unroll 8
        for (int ii = 0; ii < 64; ii++) {
            ulonglong2 w = *(const ulonglong2*)&wr[ii * 16];   // {W[h01],W[h23]}
            u64 x0 = xr0[ii];
            u64 x1 = xr1[ii];
            FMA2(a00, w.x, x0);
            FMA2(a10, w.y, x0);
            FMA2(a01, w.x, x1);
            FMA2(a11, w.y, x1);
        }
        u64* rb = &red[is * 256 + (hg * 2) * 16 + bg * 2];
        rb[0]      = a00;  // hp=hg*2,   b=2bg
        rb[16]     = a10;  // hp=hg*2+1, b=2bg
        rb[1]      = a01;
        rb[17]     = a11;
        __syncthreads();

        // Phase 2: reduce I-splits, add bias, store xp
        u64 s, u;
        ADD2(s, red[0*256 + php*16 + pb], red[1*256 + php*16 + pb]);
        ADD2(u, red[2*256 + php*16 + pb], red[3*256 + php*16 + pb]);
        ADD2(s, s, u);
        float v0, v1; UNPACK2(v0, v1, s);
        float* dst = &g_xp[(((size_t)t * NBT + bt) * Hsz + h0 + php * 2) * BTW + pb];
        dst[0]   = v0 + pbias0;
        dst[BTW] = v1 + pbias1;
    }
}

// ---------------------------------------------------------------------------
// Persistent recurrence. 128 blocks (16 ht x 8 bt), 256 threads, K-split 4.
// smem: Wt[512][32] f32 (64KB) + hs2[512][16] u64 replicated (64KB) + red (8KB)
// ---------------------------------------------------------------------------
__global__ void __launch_bounds__(256) rnn_kernel(const float* __restrict__ W_hh)
{
    extern __shared__ float smem[];
    float* Wt  = smem;                       // [512][32]: Wt[k][j]=W_hh[h0+j][k]
    u64*   hs2 = (u64*)(smem + 16384);       // [512][16]: {h[k][b], h[k][b]}
    u64*   red = (u64*)(smem + 32768);       // [4][16][16]
    const u64* Wtu = (const u64*)Wt;
    float* hs2f = (float*)hs2;

    const int blk = blockIdx.x;
    const int ht = blk & 15, bt = blk >> 4;
    const int h0 = ht * 32;
    const int tid = threadIdx.x;

    // Stage W_hh tile once, transposed (reused for all 512 steps)
    {
        const int lane_j = tid & 31, qb = tid >> 5;          // qb 0..7
        for (int r = 0; r < 16; r++) {
            int q = qb + 8 * r;                              // 0..127
            float4 w = *(const float4*)&W_hh[(h0 + lane_j) * Hsz + 4 * q];
            Wt[(4*q+0)*32 + lane_j] = w.x;
            Wt[(4*q+1)*32 + lane_j] = w.y;
            Wt[(4*q+2)*32 + lane_j] = w.z;
            Wt[(4*q+3)*32 + lane_j] = w.w;
        }
    }

    const int bg = tid & 7, hg = (tid >> 3) & 7, ks = tid >> 6;  // K-split 0..3
    const int pb = tid & 15, php = tid >> 4;
    const float invT = 1.0f / 512.0f;

    unsigned base_gen = 0;
    if (tid == 0) base_gen = *(volatile unsigned*)&g_bar_gen;

    for (int t = 0; t < Tlen; t++) {
        __syncthreads();   // prior phase-2 reads of hs2/red done; covers Wt on t=0
        // Stage h slice (32KB) from L2, replicated into hs2
        {
            const float4* hsrc = (const float4*)(g_h[t & 1] + bt * (Hsz * BTW));
            for (int j = 0; j < 8; j++) {
                int idx = tid + 256 * j;                     // 2048 float4 loads
                float4 v = __ldcg(hsrc + idx);
                u64 p0, p1, p2, p3;
                PACK2(p0, v.x, v.x); PACK2(p1, v.y, v.y);
                PACK2(p2, v.z, v.z); PACK2(p3, v.w, v.w);
                u64* dst = &hs2[idx * 4];
                dst[0] = p0; dst[1] = p1; dst[2] = p2; dst[3] = p3;
            }
        }
        // Prefetch this thread's xp values (DRAM latency hidden by GEMM)
        const size_t xbase = (((size_t)t * NBT + bt) * Hsz + h0 + php * 2) * BTW + pb;
        float xp0 = __ldg(&g_xp[xbase]);
        float xp1 = __ldg(&g_xp[xbase + BTW]);
        __syncthreads();

        // GEMM slice: 4 FFMA2 per 2 LDS.128 per k
        u64 a00 = 0, a10 = 0, a01 = 0, a11 = 0;
        const u64* hr = &hs2[(ks * 128) * 16 + bg * 2];
        const u64* wr = &Wtu[(ks * 128) * 16 + hg * 2];
        #pragma unroll 8
        for (int kk = 0; kk < 128; kk++) {
            ulonglong2 w  = *(const ulonglong2*)&wr[kk * 16];  // {W[h01],W[h23]}
            ulonglong2 hv = *(const ulonglong2*)&hr[kk * 16];  // {{hb0,hb0},{hb1,hb1}}
            FMA2(a00, w.x, hv.x);
            FMA2(a10, w.y, hv.x);
            FMA2(a01, w.x, hv.y);
            FMA2(a11, w.y, hv.y);
        }
        u64* rb = &red[ks * 256 + (hg * 2) * 16 + bg * 2];
        rb[0]  = a00;
        rb[16] = a10;
        rb[1]  = a01;
        rb[17] = a11;
        __syncthreads();

        // Phase 2: reduce K-splits, epilogue h_new = h + tanh(acc+xp)*invT
        {
            u64 s, u;
            ADD2(s, red[0*256 + php*16 + pb], red[1*256 + php*16 + pb]);
            ADD2(u, red[2*256 + php*16 + pb], red[3*256 + php*16 + pb]);
            ADD2(s, s, u);
            float v0, v1; UNPACK2(v0, v1, s);
            float hp0 = hs2f[((h0 + php*2 + 0) * 16 + pb) * 2];  // .lo of replicated pair
            float hp1 = hs2f[((h0 + php*2 + 1) * 16 + pb) * 2];
            float* hdst = g_h[(t + 1) & 1] + bt * (Hsz * BTW) + (h0 + php * 2) * BTW + pb;
            hdst[0]   = hp0 + tanhf(v0 + xp0) * invT;
            hdst[BTW] = hp1 + tanhf(v1 + xp1) * invT;
        }

        // Grid barrier (monotonic generation counter)
        __syncthreads();
        if (tid == 0) {
            __threadfence();
            unsigned target = base_gen + (unsigned)(t + 1);
            if (atomicAdd(&g_bar_count, 1u) == RNN_BLOCKS - 1) {
                atomicExch(&g_bar_count, 0u);
                __threadfence();
                atomicExch(&g_bar_gen, target);
            } else {
                while ((*(volatile unsigned*)&g_bar_gen) - base_gen < (unsigned)(t + 1)) { }
            }
        }
        __syncthreads();
    }
}

// ---------------------------------------------------------------------------
// Readout: out[b][o] = sum_k h_last[k][b] * W_out[o][k] + b_out[o]
// ---------------------------------------------------------------------------
__global__ void __launch_bounds__(128, 1) out_kernel(
    const float* __restrict__ W_out, const float* __restrict__ b_out,
    float* __restrict__ out)
{
    extern __shared__ float smem[];
    float* Wt = smem;                  // [512][32]
    float* hs = smem + Hsz * 32;       // [512][16]

    const int blk = blockIdx.x;
    const int ot = blk & 7, bt = blk >> 3;
    const int o0 = ot * 32;
    const int tid = threadIdx.x;
    const int lane_j = tid & 31;
    const int qb = tid >> 5;

    for (int q = qb; q < 128; q += 4) {
        float4 w = *(const float4*)&W_out[(o0 + lane_j) * Hsz + 4 * q];
        Wt[(4*q+0)*32 + lane_j] = w.x;
        Wt[(4*q+1)*32 + lane_j] = w.y;
        Wt[(4*q+2)*32 + lane_j] = w.z;
        Wt[(4*q+3)*32 + lane_j] = w.w;
    }
    const float4* hsrc = (const float4*)(g_h[0] + bt * (Hsz * BTW));  // T even
    for (int idx = tid; idx < (Hsz * BTW) / 4; idx += 128) {
        *((float4*)hs + idx) = hsrc[idx];
    }
    __syncthreads();

    const int b_ = tid & 15, og = tid >> 4;
    float acc0 = 0.f, acc1 = 0.f, acc2 = 0.f, acc3 = 0.f;
    #pragma unroll 8
    for (int k = 0; k < Hsz; k++) {
        float a = hs[k * 16 + b_];
        float4 w = *(const float4*)&Wt[k * 32 + og * 4];
        acc0 += a * w.x; acc1 += a * w.y; acc2 += a * w.z; acc3 += a * w.w;
    }
    int b_glob = bt * BTW + b_;
    int o = o0 + og * 4;
    out[b_glob * Osz + o + 0] = acc0 + b_out[o + 0];
    out[b_glob * Osz + o + 1] = acc1 + b_out[o + 1];
    out[b_glob * Osz + o + 2] = acc2 + b_out[o + 2];
    out[b_glob * Osz + o + 3] = acc3 + b_out[o + 3];
}

// ---------------------------------------------------------------------------
extern "C" void kernel_launch(void* const* d_in, const int* in_sizes, int n_in,
                              void* d_out, int out_size)
{
    const float* inputs = (const float*)d_in[0];
    const float* W_ih   = (const float*)d_in[1];
    const float* b_ih   = (const float*)d_in[2];
    const float* W_hh   = (const float*)d_in[3];
    const float* b_hh   = (const float*)d_in[4];
    const float* W_out  = (const float*)d_in[5];
    const float* b_out  = (const float*)d_in[6];
    const float* h0     = (const float*)d_in[7];
    float* out = (float*)d_out;

    const int SMEM_XP  = 8192 * 4 + 2 * 16 * XSROW * 8 + 1024 * 8;       // 73856 B
    const int SMEM_RNN = 16384 * 4 + Hsz * BTW * 8 + 1024 * 8;           // 139264 B
    const int SMEM_OUT = (Hsz * 32 + Hsz * BTW) * 4;                     // 98304 B
    cudaFuncSetAttribute(xp_kernel,  cudaFuncAttributeMaxDynamicSharedMemorySize, SMEM_XP);
    cudaFuncSetAttribute(rnn_kernel, cudaFuncAttributeMaxDynamicSharedMemorySize, SMEM_RNN);
    cudaFuncSetAttribute(out_kernel, cudaFuncAttributeMaxDynamicSharedMemorySize, SMEM_OUT);

    hinit_kernel<<<64, 1024>>>(h0);
    xp_kernel<<<dim3(Tlen / TQ, NBT, Hsz / 32), 256, SMEM_XP>>>(inputs, W_ih, b_ih, b_hh);
    rnn_kernel<<<RNN_BLOCKS, 256, SMEM_RNN>>>(W_hh);
    out_kernel<<<64, 128, SMEM_OUT>>>(W_out, b_out, out);
}

// round 5
// speedup vs baseline: 1.3086x; 1.0845x over previous
#include <cuda_runtime.h>
#include <math.h>

// Problem dims (fixed)
#define Bsz   128
#define Tlen  512
#define Isz   256
#define Hsz   512
#define Osz   256

// Pod decomposition: 16 independent pods x 8 blocks; each pod owns 8 batches,
// each block owns 64 h-rows of W_hh (128KB fp32 in smem).
#define PODS  16
#define PODB  8      // blocks per pod
#define PB    8      // batches per pod
#define NBT   8      // xp batch tiles (of 16)

// Packed f32x2 helpers (ptxas never emits FFMA2 from C++; inline PTX required)
#define FMA2(acc, a, b) \
    asm("fma.rn.f32x2 %0, %1, %2, %0;" : "+l"(acc) : "l"(a), "l"(b))
#define ADD2(d, a, b) \
    asm("add.rn.f32x2 %0, %1, %2;" : "=l"(d) : "l"(a), "l"(b))
#define PACK2(d, lo, hi) \
    asm("mov.b64 %0, {%1, %2};" : "=l"(d) : "f"(lo), "f"(hi))
#define UNPACK2(lo, hi, v) \
    asm("mov.b64 {%0, %1}, %2;" : "=f"(lo), "=f"(hi) : "l"(v))

typedef unsigned long long u64;

// Scratch (device globals; no runtime allocation)
__device__ float    g_xp[(size_t)Tlen * PODS * Hsz * PB]; // [t][pod][h][8]
__device__ float    g_h[2][PODS * Hsz * PB];              // [parity][pod][k][8]
__device__ unsigned g_pbar_count[PODS * 32];              // 128B-padded per pod
__device__ unsigned g_pbar_gen[PODS * 32];

// ---------------------------------------------------------------------------
// h init: g_h[0][pod][k][b] = h0[k]
// ---------------------------------------------------------------------------
__global__ void hinit_kernel(const float* __restrict__ h0) {
    int idx = blockIdx.x * blockDim.x + threadIdx.x;   // over 16*512*8 = 65536
    int k = (idx >> 3) & (Hsz - 1);
    g_h[0][idx] = h0[k];
}

// ---------------------------------------------------------------------------
// x_proj: xp[t][pod][h][b] = sum_i inputs[b][t][i]*W_ih[h][i] + b_ih[h]+b_hh[h]
// grid (Tlen/TQ, NBT, Hsz/32), 256 threads. FFMA2, I-split 4.
// ---------------------------------------------------------------------------
#define TQ  8
#define XSROW 257

__global__ void __launch_bounds__(256) xp_kernel(
    const float* __restrict__ inputs, const float* __restrict__ W_ih,
    const float* __restrict__ b_ih,   const float* __restrict__ b_hh)
{
    extern __shared__ float smem[];
    float* Wt  = smem;                              // [256][32]: Wt[i][j]=W_ih[h0+j][i]
    u64*   xs2 = (u64*)(smem + 8192);               // [16][257]: xs2[b][i]={x,x}
    u64*   red = (u64*)(smem + 8192 + 2 * 16 * XSROW);  // [4][16][16]
    const u64* Wtu = (const u64*)Wt;

    const int tq = blockIdx.x, bt = blockIdx.y, ht = blockIdx.z;
    const int h0 = ht * 32, b0 = bt * 16;
    const int tid = threadIdx.x;

    // Stage W_ih tile transposed (once)
    {
        const int lane_j = tid & 31, qb = tid >> 5;          // qb 0..7
        for (int r = 0; r < 8; r++) {
            int q = qb + 8 * r;                              // 0..63
            float4 w = *(const float4*)&W_ih[(h0 + lane_j) * Isz + 4 * q];
            Wt[(4*q+0)*32 + lane_j] = w.x;
            Wt[(4*q+1)*32 + lane_j] = w.y;
            Wt[(4*q+2)*32 + lane_j] = w.z;
            Wt[(4*q+3)*32 + lane_j] = w.w;
        }
    }

    const int bg = tid & 7, hg = (tid >> 3) & 7, is = tid >> 6;  // I-split 0..3
    const int pb = tid & 15, php = tid >> 4;                     // phase-2 roles
    const int pod = bt * 2 + (pb >> 3), bi = pb & 7;
    const float pbias0 = b_ih[h0 + php*2 + 0] + b_hh[h0 + php*2 + 0];
    const float pbias1 = b_ih[h0 + php*2 + 1] + b_hh[h0 + php*2 + 1];

    for (int tt = 0; tt < TQ; tt++) {
        const int t = tq * TQ + tt;
        __syncthreads();   // xs2/red reuse; covers Wt on first iter
        // Stage x tile replicated: xs2[b][i] = {x,x}
        for (int j = 0; j < 4; j++) {
            int idx = tid + 256 * j;                 // 1024 float4 loads
            int r = idx >> 6, q = idx & 63;
            float4 x = *(const float4*)&inputs[((size_t)(b0 + r) * Tlen + t) * Isz + 4 * q];
            u64 p0, p1, p2, p3;
            PACK2(p0, x.x, x.x); PACK2(p1, x.y, x.y);
            PACK2(p2, x.z, x.z); PACK2(p3, x.w, x.w);
            u64* dst = &xs2[r * XSROW + 4 * q];
            dst[0] = p0; dst[1] = p1; dst[2] = p2; dst[3] = p3;
        }
        __syncthreads();

        u64 a00 = 0, a10 = 0, a01 = 0, a11 = 0;
        const u64* xr0 = &xs2[(2 * bg + 0) * XSROW + is * 64];
        const u64* xr1 = &xs2[(2 * bg + 1) * XSROW + is * 64];
        const u64* wr  = &Wtu[(is * 64) * 16 + hg * 2];
        #pragma unroll 8
        for (int ii = 0; ii < 64; ii++) {
            ulonglong2 w = *(const ulonglong2*)&wr[ii * 16];
            u64 x0 = xr0[ii];
            u64 x1 = xr1[ii];
            FMA2(a00, w.x, x0);
            FMA2(a10, w.y, x0);
            FMA2(a01, w.x, x1);
            FMA2(a11, w.y, x1);
        }
        u64* rb = &red[is * 256 + (hg * 2) * 16 + bg * 2];
        rb[0]  = a00;
        rb[16] = a10;
        rb[1]  = a01;
        rb[17] = a11;
        __syncthreads();

        // Phase 2: reduce I-splits, add bias, store xp (new pod layout)
        u64 s, u;
        ADD2(s, red[0*256 + php*16 + pb], red[1*256 + php*16 + pb]);
        ADD2(u, red[2*256 + php*16 + pb], red[3*256 + php*16 + pb]);
        ADD2(s, s, u);
        float v0, v1; UNPACK2(v0, v1, s);
        float* dst = &g_xp[(((size_t)t * PODS + pod) * Hsz + h0 + php * 2) * PB + bi];
        dst[0]  = v0 + pbias0;
        dst[PB] = v1 + pbias1;
    }
}

// ---------------------------------------------------------------------------
// Persistent recurrence. 128 blocks = 16 pods x 8. Block = 64 h-rows x 8 b.
// smem: Wt[512][64] f32 (128KB) + hs2[512][8] u64 replicated (32KB) + red (8KB)
// Per step: block GEMM 8x64x512, epilogue, pod-local (8-block) barrier.
// ---------------------------------------------------------------------------
__global__ void __launch_bounds__(256) rnn_kernel(const float* __restrict__ W_hh)
{
    extern __shared__ float smem[];
    float* Wt  = smem;                              // [512][64]: Wt[k][j]=W_hh[h0+j][k]
    u64*   hs2 = (u64*)(smem + Hsz * 64);           // [512][8]: {h[k][b], h[k][b]}
    u64*   red = (u64*)(smem + Hsz * 64 + Hsz * PB * 2);  // [4][32][8]
    const u64* Wtu = (const u64*)Wt;
    float* hs2f = (float*)hs2;

    const int blk = blockIdx.x;
    const int pod = blk >> 3, ht = blk & 7;
    const int h0 = ht * 64;
    const int tid = threadIdx.x;

    // Stage this block's 64-row W_hh slice once (reused all 512 steps)
    {
        const int j = tid & 63, qg = tid >> 6;
        for (int q = qg; q < 128; q += 4) {
            float4 w = *(const float4*)&W_hh[(h0 + j) * Hsz + 4 * q];
            Wt[(4*q+0)*64 + j] = w.x;
            Wt[(4*q+1)*64 + j] = w.y;
            Wt[(4*q+2)*64 + j] = w.z;
            Wt[(4*q+3)*64 + j] = w.w;
        }
    }

    const int bg = tid & 3, hg = (tid >> 2) & 15, ks = tid >> 6;  // K-split 4
    const int pb = tid & 7, php = tid >> 3;                       // phase-2 roles
    const float invT = 1.0f / 512.0f;

    unsigned base_gen = 0;
    if (tid == 0) base_gen = *(volatile unsigned*)&g_pbar_gen[pod * 32];

    for (int t = 0; t < Tlen; t++) {
        __syncthreads();   // covers W staging on t=0; hs2/red reuse
        // Stage pod h slice (16KB) from L2, replicated into hs2
        {
            const float4* hsrc = (const float4*)(g_h[t & 1] + pod * (Hsz * PB));
            for (int j2 = 0; j2 < 4; j2++) {
                int idx = tid + 256 * j2;                        // 1024 float4
                float4 v = __ldcg(hsrc + idx);
                u64 p0, p1, p2, p3;
                PACK2(p0, v.x, v.x); PACK2(p1, v.y, v.y);
                PACK2(p2, v.z, v.z); PACK2(p3, v.w, v.w);
                u64* dst = &hs2[idx * 4];
                dst[0] = p0; dst[1] = p1; dst[2] = p2; dst[3] = p3;
            }
        }
        // Prefetch xp (DRAM latency hidden by GEMM)
        const size_t xbase = (((size_t)t * PODS + pod) * Hsz + h0 + php * 2) * PB + pb;
        float xp0 = __ldg(&g_xp[xbase]);
        float xp1 = __ldg(&g_xp[xbase + PB]);
        __syncthreads();

        // GEMM slice: thread tile 4h x 2b, 4 FFMA2 per 2 LDS.128 per k
        u64 a00 = 0, a10 = 0, a01 = 0, a11 = 0;
        const u64* hr = &hs2[(ks * 128) * PB + bg * 2];
        const u64* wr = &Wtu[(ks * 128) * 32 + hg * 2];
        #pragma unroll 8
        for (int kk = 0; kk < 128; kk++) {
            ulonglong2 w  = *(const ulonglong2*)&wr[kk * 32];  // h-pairs {4hg..},{4hg+2..}
            ulonglong2 hv = *(const ulonglong2*)&hr[kk * 8];   // {{b0,b0},{b1,b1}}
            FMA2(a00, w.x, hv.x);
            FMA2(a10, w.y, hv.x);
            FMA2(a01, w.x, hv.y);
            FMA2(a11, w.y, hv.y);
        }
        u64* rb = &red[ks * 256 + (2 * hg) * 8 + 2 * bg];
        rb[0] = a00;   // hpair 2hg,   b 2bg
        rb[8] = a10;   // hpair 2hg+1, b 2bg
        rb[1] = a01;
        rb[9] = a11;
        __syncthreads();

        // Phase 2: reduce K-splits, epilogue h_new = h + tanh(acc+xp)*invT
        {
            u64 s, u;
            ADD2(s, red[0*256 + php*8 + pb], red[1*256 + php*8 + pb]);
            ADD2(u, red[2*256 + php*8 + pb], red[3*256 + php*8 + pb]);
            ADD2(s, s, u);
            float v0, v1; UNPACK2(v0, v1, s);
            float hp0 = hs2f[((h0 + php*2 + 0) * PB + pb) * 2];
            float hp1 = hs2f[((h0 + php*2 + 1) * PB + pb) * 2];
            float* hdst = g_h[(t + 1) & 1] + pod * (Hsz * PB) + (h0 + php * 2) * PB + pb;
            hdst[0]  = hp0 + tanhf(v0 + xp0) * invT;
            hdst[PB] = hp1 + tanhf(v1 + xp1) * invT;
        }

        // Pod-local barrier (8 blocks, monotonic generation counter)
        __syncthreads();
        if (tid == 0) {
            __threadfence();
            unsigned target = base_gen + (unsigned)(t + 1);
            if (atomicAdd(&g_pbar_count[pod * 32], 1u) == PODB - 1) {
                atomicExch(&g_pbar_count[pod * 32], 0u);
                __threadfence();
                atomicExch(&g_pbar_gen[pod * 32], target);
            } else {
                while ((*(volatile unsigned*)&g_pbar_gen[pod * 32]) - base_gen < (unsigned)(t + 1)) { }
            }
        }
        __syncthreads();
    }
}

// ---------------------------------------------------------------------------
// Readout: out[b][o] = sum_k h_last[k][b] * W_out[o][k] + b_out[o]
// grid 64 blocks (8 ot x 8 bt of 16 batches = pods 2bt..2bt+1)
// ---------------------------------------------------------------------------
__global__ void __launch_bounds__(128, 1) out_kernel(
    const float* __restrict__ W_out, const float* __restrict__ b_out,
    float* __restrict__ out)
{
    extern __shared__ float smem[];
    float* Wt = smem;                  // [512][32]
    float* hs = smem + Hsz * 32;       // [2 pods][512 k][8 b] raw copy

    const int blk = blockIdx.x;
    const int ot = blk & 7, bt = blk >> 3;
    const int o0 = ot * 32;
    const int tid = threadIdx.x;
    const int lane_j = tid & 31;
    const int qb = tid >> 5;

    for (int q = qb; q < 128; q += 4) {
        float4 w = *(const float4*)&W_out[(o0 + lane_j) * Hsz + 4 * q];
        Wt[(4*q+0)*32 + lane_j] = w.x;
        Wt[(4*q+1)*32 + lane_j] = w.y;
        Wt[(4*q+2)*32 + lane_j] = w.z;
        Wt[(4*q+3)*32 + lane_j] = w.w;
    }
    // T=512 even -> final parity 0. Two pods' slices are contiguous.
    const float4* hsrc = (const float4*)(g_h[0] + (bt * 2) * (Hsz * PB));
    for (int idx = tid; idx < (2 * Hsz * PB) / 4; idx += 128) {
        *((float4*)hs + idx) = hsrc[idx];
    }
    __syncthreads();

    const int b_ = tid & 15, og = tid >> 4;
    const float* hsb = hs + (b_ >> 3) * (Hsz * PB) + (b_ & 7);
    float acc0 = 0.f, acc1 = 0.f, acc2 = 0.f, acc3 = 0.f;
    #pragma unroll 8
    for (int k = 0; k < Hsz; k++) {
        float a = hsb[k * PB];
        float4 w = *(const float4*)&Wt[k * 32 + og * 4];
        acc0 += a * w.x; acc1 += a * w.y; acc2 += a * w.z; acc3 += a * w.w;
    }
    int b_glob = bt * 16 + b_;
    int o = o0 + og * 4;
    out[b_glob * Osz + o + 0] = acc0 + b_out[o + 0];
    out[b_glob * Osz + o + 1] = acc1 + b_out[o + 1];
    out[b_glob * Osz + o + 2] = acc2 + b_out[o + 2];
    out[b_glob * Osz + o + 3] = acc3 + b_out[o + 3];
}

// ---------------------------------------------------------------------------
extern "C" void kernel_launch(void* const* d_in, const int* in_sizes, int n_in,
                              void* d_out, int out_size)
{
    const float* inputs = (const float*)d_in[0];
    const float* W_ih   = (const float*)d_in[1];
    const float* b_ih   = (const float*)d_in[2];
    const float* W_hh   = (const float*)d_in[3];
    const float* b_hh   = (const float*)d_in[4];
    const float* W_out  = (const float*)d_in[5];
    const float* b_out  = (const float*)d_in[6];
    const float* h0     = (const float*)d_in[7];
    float* out = (float*)d_out;

    const int SMEM_XP  = 8192 * 4 + 2 * 16 * XSROW * 8 + 1024 * 8;        // 73856 B
    const int SMEM_RNN = Hsz * 64 * 4 + Hsz * PB * 8 + 1024 * 8;          // 172032 B
    const int SMEM_OUT = (Hsz * 32 + 2 * Hsz * PB) * 4;                   // 98304 B
    cudaFuncSetAttribute(xp_kernel,  cudaFuncAttributeMaxDynamicSharedMemorySize, SMEM_XP);
    cudaFuncSetAttribute(rnn_kernel, cudaFuncAttributeMaxDynamicSharedMemorySize, SMEM_RNN);
    cudaFuncSetAttribute(out_kernel, cudaFuncAttributeMaxDynamicSharedMemorySize, SMEM_OUT);

    hinit_kernel<<<64, 1024>>>(h0);
    xp_kernel<<<dim3(Tlen / TQ, NBT, Hsz / 32), 256, SMEM_XP>>>(inputs, W_ih, b_ih, b_hh);
    rnn_kernel<<<PODS * PODB, 256, SMEM_RNN>>>(W_hh);
    out_kernel<<<64, 128, SMEM_OUT>>>(W_out, b_out, out);
}